// round 11
// baseline (speedup 1.0000x reference)
#include <cuda_runtime.h>
#include <cstddef>

#define N_ROWS 8192
#define N_COLS 8192
#define THREADS 256
#define N_STEPS 100
#define HALF_STEPS 50
#define EPT (N_COLS / 64)   // elements per thread within a 64-thread group = 128
#define MAXC 14             // max local steps per group (group 3 has 14)

// Cross-kernel scratch (device globals: allowed; no allocation).
__device__ float g_loss[N_STEPS][N_ROWS];   // losses[step][row]
__device__ float g_aux[2][N_ROWS];          // [0]=rmin, [1]=rmax per row

__device__ __forceinline__ float shfl_add(float v) {
    #pragma unroll
    for (int o = 16; o; o >>= 1) v += __shfl_xor_sync(0xFFFFFFFFu, v, o);
    return v;
}

// Row is pre-scaled: row_sm[k] = x[k] * K, K = 12750/R, so u_i = |V| * (1/i)
// with (1/i) a COMPILE-TIME constant -> dd uses FFMA-imm (rt1).
// Per pair (steps s0=BASE+2j, s1=BASE+2j+1; i = s+1):
//   rr2 = fma2(VV, wp, M2) = M + round(u)        [fma rt3]
//   rc  = min(rr, M+cb) per half                 [alu]
//   nq2 = sub2(M2, rc2) = -q exact               [fma rt2]
//   dd  = fma(V, imm(1/i), nq) per half          [fma rt1 x2, FFMA-imm]
//   acc2 += dd2*dd2                              [fma rt2]
template<int BASE, int NPAIR>
__device__ __forceinline__ void run_group(
    const float* __restrict__ row_sm,
    float (*partial)[MAXC], int l64, int warp, int lane,
    unsigned long long M2)
{
    unsigned long long wp[NPAIR], app[NPAIR];
    #pragma unroll
    for (int j = 0; j < NPAIR; j++) {
        float w0 = 1.0f / (float)(BASE + 2 * j + 1);
        float w1 = 1.0f / (float)(BASE + 2 * j + 2);
        asm("mov.b64 %0, {%1,%2};" : "=l"(wp[j]) : "f"(w0), "f"(w1));
        app[j] = 0ULL;
    }

    #pragma unroll 2
    for (int k = 0; k < EPT; k++) {
        float xv = row_sm[l64 + (k << 6)];                       // x*K (signed)
        unsigned xb = __float_as_uint(xv);
        float ax = __uint_as_float(xb & 0x7FFFFFFFu);            // V = |x|*K
        float cb = __uint_as_float(0x4B40007Fu + (xb >> 31));    // M+127 / M+128
        unsigned long long aa;
        asm("mov.b64 %0, {%1,%1};" : "=l"(aa) : "f"(ax));
        #pragma unroll
        for (int j = 0; j < NPAIR; j++) {
            float nq0, nq1;
            asm("{\n\t"
                ".reg .f32 r0,r1,c0,c1;\n\t"
                ".reg .b64 rr;\n\t"
                "fma.rn.f32x2 rr, %2, %3, %4;\n\t"   // M + round(u)   [rt3]
                "mov.b64 {r0,r1}, rr;\n\t"
                "min.f32 c0, r0, %5;\n\t"            // clamp          [alu]
                "min.f32 c1, r1, %5;\n\t"
                "mov.b64 rr, {c0,c1};\n\t"
                "sub.rn.f32x2 rr, %4, rr;\n\t"       // -q exact       [rt2]
                "mov.b64 {%0,%1}, rr;\n\t"
                "}"
                : "=f"(nq0), "=f"(nq1)
                : "l"(aa), "l"(wp[j]), "l"(M2), "f"(cb));
            // FFMA-imm (rt1): multiplier is a compile-time literal 1/i.
            float dd0 = __fmaf_rn(ax, 1.0f / (float)(BASE + 2 * j + 1), nq0);
            float dd1 = __fmaf_rn(ax, 1.0f / (float)(BASE + 2 * j + 2), nq1);
            asm("{\n\t"
                ".reg .b64 dd;\n\t"
                "mov.b64 dd, {%1,%2};\n\t"
                "fma.rn.f32x2 %0, dd, dd, %0;\n\t"   // acc += d*d     [rt2]
                "}"
                : "+l"(app[j]) : "f"(dd0), "f"(dd1));
        }
    }

    #pragma unroll
    for (int j = 0; j < NPAIR; j++) {
        float a0, a1;
        asm("mov.b64 {%0,%1}, %2;" : "=f"(a0), "=f"(a1) : "l"(app[j]));
        a0 = shfl_add(a0);
        a1 = shfl_add(a1);
        if (lane == 0) { partial[warp][2 * j] = a0; partial[warp][2 * j + 1] = a1; }
    }
}

// Kernel 1: grid (N_ROWS, 2). blockIdx.y selects which 50 steps this block owns.
__global__ __launch_bounds__(THREADS)
void mse_losses_kernel(const float* __restrict__ x, unsigned long long M2) {
    __shared__ float row_sm[N_COLS];
    __shared__ float s2k[HALF_STEPS];      // scale^2 / 8192 for this half
    __shared__ float partial[8][MAXC];
    __shared__ float red_min[8], red_max[8];
    __shared__ float Rsh, Ksh;

    const int row  = blockIdx.x;
    const int half = blockIdx.y;
    const int tid  = threadIdx.x;
    const int warp = tid >> 5;
    const int lane = tid & 31;
    const float* xr = x + (size_t)row * N_COLS;

    // ---- Phase A: load row to smem, compute row min/max ----
    float mn = 3.0e38f, mx = -3.0e38f;
    const float4* xr4 = (const float4*)xr;
    float4* row4 = (float4*)row_sm;
    #pragma unroll
    for (int k = 0; k < N_COLS / 4 / THREADS; k++) {   // 8 iterations
        float4 v = xr4[tid + k * THREADS];
        row4[tid + k * THREADS] = v;
        mn = fminf(mn, fminf(fminf(v.x, v.y), fminf(v.z, v.w)));
        mx = fmaxf(mx, fmaxf(fmaxf(v.x, v.y), fmaxf(v.z, v.w)));
    }
    #pragma unroll
    for (int o = 16; o; o >>= 1) {
        mn = fminf(mn, __shfl_xor_sync(0xFFFFFFFFu, mn, o));
        mx = fmaxf(mx, __shfl_xor_sync(0xFFFFFFFFu, mx, o));
    }
    if (lane == 0) { red_min[warp] = mn; red_max[warp] = mx; }
    __syncthreads();
    if (tid == 0) {
        float m = red_min[0], M = red_max[0];
        #pragma unroll
        for (int w = 1; w < 8; w++) { m = fminf(m, red_min[w]); M = fmaxf(M, red_max[w]); }
        float R = fmaxf(fabsf(m), M);          // range_val = max(|min|, max)
        Rsh = R;
        Ksh = __fdiv_rn(12750.0f, R);          // K: u_i = |x|*K * (1/i)
        if (half == 0) {
            g_aux[0][row] = m;
            g_aux[1][row] = M;
        }
    }
    __syncthreads();

    // ---- Phase A2: pre-scale row by K (each thread rescales its own slice) ----
    {
        float Kv = Ksh;
        #pragma unroll
        for (int k = 0; k < N_COLS / 4 / THREADS; k++) {
            float4 v = row4[tid + k * THREADS];
            v.x *= Kv; v.y *= Kv; v.z *= Kv; v.w *= Kv;
            row4[tid + k * THREADS] = v;
        }
    }

    // ---- Phase B: s2k table for this half's 50 steps ----
    if (tid < HALF_STEPS) {
        float R = Rsh;
        int   sg = half * HALF_STEPS + tid;          // global step index 0..99
        float thres = __fdiv_rn(R, 100.0f) * (float)(sg + 1);
        float scale = fmaxf(__fdiv_rn(thres, 127.5f), 1.1920928955078125e-07f);
        s2k[tid] = scale * scale * (1.0f / 8192.0f);
    }
    __syncthreads();

    // ---- Phase C: 4 groups x {6,6,6,7} pairs = 50 steps; BASE is the GLOBAL
    // 0-based step offset (compile-time for the 1/i immediates) ----
    const int grp = tid >> 6;
    const int l64 = tid & 63;
    if (half == 0) {
        if (grp == 0)      run_group< 0, 6>(row_sm, partial, l64, warp, lane, M2);
        else if (grp == 1) run_group<12, 6>(row_sm, partial, l64, warp, lane, M2);
        else if (grp == 2) run_group<24, 6>(row_sm, partial, l64, warp, lane, M2);
        else               run_group<36, 7>(row_sm, partial, l64, warp, lane, M2);
    } else {
        if (grp == 0)      run_group<50, 6>(row_sm, partial, l64, warp, lane, M2);
        else if (grp == 1) run_group<62, 6>(row_sm, partial, l64, warp, lane, M2);
        else if (grp == 2) run_group<74, 6>(row_sm, partial, l64, warp, lane, M2);
        else               run_group<86, 7>(row_sm, partial, l64, warp, lane, M2);
    }
    __syncthreads();

    // ---- Phase D: combine warp pairs, write losses to scratch ----
    if (tid < HALF_STEPS) {
        int s = tid;                       // local step 0..49
        int g  = (s < 36) ? (s / 12) : 3;
        int jj = (s < 36) ? (s % 12) : (s - 36);
        float sum = partial[2 * g][jj] + partial[2 * g + 1][jj];
        g_loss[half * HALF_STEPS + s][row] = sum * s2k[s];
    }
}

// Kernel 2: per-row sequential argmin scan (matches lax.scan semantics).
__global__ __launch_bounds__(256)
void mse_argmin_kernel(float* __restrict__ out) {
    int row = blockIdx.x * 256 + threadIdx.x;
    if (row >= N_ROWS) return;
    float rmin = g_aux[0][row];
    float rmax = g_aux[1][row];
    float R = fmaxf(fabsf(rmin), rmax);
    float step_sz = __fdiv_rn(R, 100.0f);      // identical expr to kernel1
    float best = 1.0e9f;
    float bmin = rmin, bmax = rmax;
    for (int j = 0; j < N_STEPS; j++) {
        float L = g_loss[j][row];               // coalesced, L2-hot
        float thres = step_sz * (float)(j + 1);
        if (L < best) { best = L; bmin = -thres; bmax = thres; }
    }
    out[row] = bmin;
    out[N_ROWS + row] = bmax;
}

extern "C" void kernel_launch(void* const* d_in, const int* in_sizes, int n_in,
                              void* d_out, int out_size) {
    const float* x = (const float*)d_in[0];
    float* out = (float*)d_out;
    dim3 grid1(N_ROWS, 2);
    mse_losses_kernel<<<grid1, THREADS>>>(x, 0x4B4000004B400000ULL);
    mse_argmin_kernel<<<N_ROWS / 256, 256>>>(out);
}